// round 17
// baseline (speedup 1.0000x reference)
#include <cuda_runtime.h>
#include <cuda_bf16.h>
#include <cuda_fp16.h>
#include <cstdint>

#define N_NODES 50000
#define F1 128
#define NCLS 16
#define EMAX 1600000
#define NB_SCAN ((N_NODES + 255) / 256)   // 196

// ---------------- scratch (static device globals; no allocation) ----------------
__device__ int    g_cnt[N_NODES];
__device__ int    g_start[N_NODES + 1];
__device__ int    g_cursor[N_NODES];
__device__ int    g_srcl[EMAX];
__device__ float  g_inv[N_NODES];
__device__ __half g_Ah[N_NODES * F1];     // layer1 gemm output h (UNSCALED), fp16
__device__ float  g_z[N_NODES * NCLS];    // z = h2 @ Wlin^T, fp32
__device__ int    g_bsum[256];
__device__ int    g_boff[256];
__device__ int    g_is64;
// pre-split weights, padded to K=512, layout [n][512] bf16
__device__ __nv_bfloat16 g_W1hi[128 * 512];
__device__ __nv_bfloat16 g_W1lo[128 * 512];
__device__ __nv_bfloat16 g_W2hi[128 * 512];
__device__ __nv_bfloat16 g_W2lo[128 * 512];

// ---------------- mma/ldmatrix wrappers (base ISA, sm_80+) ----------------
__device__ __forceinline__ uint32_t s2u(const void* p) {
    uint32_t a;
    asm("{ .reg .u64 t; cvta.to.shared.u64 t, %1; cvt.u32.u64 %0, t; }" : "=r"(a) : "l"(p));
    return a;
}
__device__ __forceinline__ void ldsm4(uint32_t& r0, uint32_t& r1, uint32_t& r2, uint32_t& r3,
                                      uint32_t addr) {
    asm volatile("ldmatrix.sync.aligned.m8n8.x4.shared.b16 {%0,%1,%2,%3}, [%4];"
                 : "=r"(r0), "=r"(r1), "=r"(r2), "=r"(r3) : "r"(addr));
}
__device__ __forceinline__ void mma16816(float* c, const uint32_t* a, const uint32_t* b) {
    asm volatile(
        "mma.sync.aligned.m16n8k16.row.col.f32.bf16.bf16.f32 "
        "{%0,%1,%2,%3}, {%4,%5,%6,%7}, {%8,%9}, {%0,%1,%2,%3};"
        : "+f"(c[0]), "+f"(c[1]), "+f"(c[2]), "+f"(c[3])
        : "r"(a[0]), "r"(a[1]), "r"(a[2]), "r"(a[3]), "r"(b[0]), "r"(b[1]));
}

// ---------------- fused init: zero counts + dtype detect ----------------
__global__ void k_init(const int* ei) {
    int i = blockIdx.x * blockDim.x + threadIdx.x;
    if (i < N_NODES) g_cnt[i] = 0;
    if (i == 0) {
        int ok64 = 1;
        #pragma unroll 1
        for (int q = 0; q < 64; q++) ok64 &= (ei[2 * q + 1] == 0);
        g_is64 = ok64;
    }
}

// ---------------- CSR build ----------------
__global__ __launch_bounds__(256) void k_hist(const void* idx, long long E) {
    long long e = (long long)blockIdx.x * blockDim.x + threadIdx.x;
    if (e >= E) return;
    int d;
    if (g_is64) d = (int)((const long long*)idx)[E + e];
    else        d = ((const int*)idx)[E + e];
    atomicAdd(&g_cnt[d], 1);
}

__global__ __launch_bounds__(256) void k_scan1() {
    int i = blockIdx.x * 256 + threadIdx.x;
    int lane = threadIdx.x & 31, wid = threadIdx.x >> 5;
    int c = (i < N_NODES) ? g_cnt[i] : 0;
    int s = c;
    #pragma unroll
    for (int off = 16; off; off >>= 1) s += __shfl_xor_sync(0xffffffffu, s, off);
    __shared__ int ws[8];
    if (lane == 0) ws[wid] = s;
    __syncthreads();
    if (threadIdx.x == 0) {
        int tot = 0;
        #pragma unroll
        for (int w = 0; w < 8; w++) tot += ws[w];
        g_bsum[blockIdx.x] = tot;
    }
}

__global__ __launch_bounds__(256) void k_scan2() {
    __shared__ int s[256];
    int t = threadIdx.x;
    int v = (t < NB_SCAN) ? g_bsum[t] : 0;
    s[t] = v;
    __syncthreads();
    for (int off = 1; off < 256; off <<= 1) {
        int u = (t >= off) ? s[t - off] : 0;
        __syncthreads();
        s[t] += u;
        __syncthreads();
    }
    g_boff[t] = s[t] - v;
    if (t == 255) g_start[N_NODES] = s[255];
}

__global__ __launch_bounds__(256) void k_scan3() {
    int i = blockIdx.x * 256 + threadIdx.x;
    int t = threadIdx.x, lane = t & 31, wid = t >> 5;
    int c = (i < N_NODES) ? g_cnt[i] : 0;
    int incl = c;
    #pragma unroll
    for (int off = 1; off < 32; off <<= 1) {
        int u = __shfl_up_sync(0xffffffffu, incl, off);
        if (lane >= off) incl += u;
    }
    __shared__ int ws[8];
    if (lane == 31) ws[wid] = incl;
    __syncthreads();
    if (t == 0) {
        int run = 0;
        #pragma unroll
        for (int w = 0; w < 8; w++) { int x = ws[w]; ws[w] = run; run += x; }
    }
    __syncthreads();
    if (i < N_NODES) {
        int excl = incl - c + ws[wid] + g_boff[blockIdx.x];
        g_start[i]  = excl;
        g_cursor[i] = excl;
        g_inv[i]    = rsqrtf((float)c + 1.0f);
    }
}

__global__ __launch_bounds__(256) void k_fill(const void* idx, long long E) {
    long long e = (long long)blockIdx.x * blockDim.x + threadIdx.x;
    if (e >= E) return;
    int s, d;
    if (g_is64) {
        s = (int)((const long long*)idx)[e];
        d = (int)((const long long*)idx)[E + e];
    } else {
        s = ((const int*)idx)[e];
        d = ((const int*)idx)[E + e];
    }
    int pos = atomicAdd(&g_cursor[d], 1);
    g_srcl[pos] = s;
}

// ---------------- weight pre-split: W[n][k] fp32 -> hi/lo bf16 padded [n][512] ----------------
__global__ __launch_bounds__(256) void k_wsplit(const float* __restrict__ W,
                                                __nv_bfloat16* __restrict__ hi,
                                                __nv_bfloat16* __restrict__ lo, int K) {
    int i = blockIdx.x * 256 + threadIdx.x;
    if (i >= 128 * 512) return;
    int n = i >> 9, k = i & 511;
    float v = (k < K) ? W[n * K + k] : 0.0f;
    __nv_bfloat16 h = __float2bfloat16(v);
    hi[i] = h;
    lo[i] = __float2bfloat16(v - __bfloat162float(h));
}

// ---------------- shared GEMM machinery (R12-verified config) ----------------
#define LDB 80
#define TILE_B (128 * LDB)          // 10240
#define CH_BUF (4 * TILE_B)         // 40960: [XHI, XLO, WHI, WLO]
#define GEMM_SMEM (2 * CH_BUF)      // 81920
#define ROWB 272                    // h2 smem staging row stride (bytes)
#define CSLD 132                    // fused C smem tile: words per row (float4-aligned)
#define WLS_OFF (2 * CH_BUF)                          // Wlin at 81920
#define CS_OFF  (WLS_OFF + NCLS * F1 * 4)             // C tile at 90112
#define FUSED_SMEM (CS_OFF + 128 * CSLD * 4)          // 157696

#define CVT_STORE(bo)                                                            \
    do {                                                                         \
        uint32_t hh[8], ll[8];                                                   \
        _Pragma("unroll")                                                        \
        for (int p = 0; p < 8; p++) {                                            \
            __nv_bfloat16 ha = __float2bfloat16(v[2 * p]);                       \
            __nv_bfloat16 hb = __float2bfloat16(v[2 * p + 1]);                   \
            __nv_bfloat16 la = __float2bfloat16(v[2 * p]     - __bfloat162float(ha)); \
            __nv_bfloat16 lb = __float2bfloat16(v[2 * p + 1] - __bfloat162float(hb)); \
            hh[p] = (uint32_t)__bfloat16_as_ushort(ha) | ((uint32_t)__bfloat16_as_ushort(hb) << 16); \
            ll[p] = (uint32_t)__bfloat16_as_ushort(la) | ((uint32_t)__bfloat16_as_ushort(lb) << 16); \
        }                                                                        \
        char* base = smem + (bo) + cbase;                                        \
        *(uint4*)(base)                   = make_uint4(hh[0], hh[1], hh[2], hh[3]); \
        *(uint4*)(base + 16)              = make_uint4(hh[4], hh[5], hh[6], hh[7]); \
        *(uint4*)(base + TILE_B)          = make_uint4(ll[0], ll[1], ll[2], ll[3]); \
        *(uint4*)(base + TILE_B + 16)     = make_uint4(ll[4], ll[5], ll[6], ll[7]); \
        *(uint4*)(base + 2 * TILE_B)      = pwh[0];                              \
        *(uint4*)(base + 2 * TILE_B + 16) = pwh[1];                              \
        *(uint4*)(base + 3 * TILE_B)      = pwl[0];                              \
        *(uint4*)(base + 3 * TILE_B + 16) = pwl[1];                              \
    } while (0)

#define LOADW(CH)                                                               \
    do {                                                                        \
        const __nv_bfloat16* wh_ = Whi + (size_t)crow * 512 + (CH) * 32 + cko;  \
        const __nv_bfloat16* wl_ = Wlo + (size_t)crow * 512 + (CH) * 32 + cko;  \
        pwh[0] = *(const uint4*)(wh_);  pwh[1] = *(const uint4*)(wh_ + 8);      \
        pwl[0] = *(const uint4*)(wl_);  pwl[1] = *(const uint4*)(wl_ + 8);      \
    } while (0)

#define LOADX(CH, K)                                                            \
    do {                                                                        \
        const int ks_ = (CH) * 32 + cko;                                        \
        if (rok && ks_ + 16 <= (K)) {                                           \
            _Pragma("unroll")                                                   \
            for (int q = 0; q < 4; q++) {                                       \
                float4 f = *(const float4*)(Xrow + ks_ + q * 4);                \
                v[q * 4 + 0] = f.x; v[q * 4 + 1] = f.y;                         \
                v[q * 4 + 2] = f.z; v[q * 4 + 3] = f.w;                         \
            }                                                                   \
        } else {                                                                \
            _Pragma("unroll")                                                   \
            for (int q = 0; q < 16; q++)                                        \
                v[q] = (rok && (ks_ + q) < (K)) ? Xrow[ks_ + q] : 0.0f;         \
        }                                                                       \
        LOADW(CH);                                                              \
    } while (0)

#define MMA_CHUNK(bo)                                                           \
    do {                                                                        \
        _Pragma("unroll")                                                       \
        for (int kb = 0; kb < 2; kb++) {                                        \
            uint32_t ah[2][4], al[2][4], bh[8][2], bl[8][2];                    \
            _Pragma("unroll")                                                   \
            for (int mt = 0; mt < 2; mt++) {                                    \
                uint32_t ro = (uint32_t)(wm * 32 + mt * 16 + a_row) * LDB + kb * 32 + a_koff; \
                ldsm4(ah[mt][0], ah[mt][1], ah[mt][2], ah[mt][3], sb + (bo) + ro);            \
                ldsm4(al[mt][0], al[mt][1], al[mt][2], al[mt][3], sb + (bo) + TILE_B + ro);   \
            }                                                                   \
            _Pragma("unroll")                                                   \
            for (int p = 0; p < 4; p++) {                                       \
                uint32_t ro = (uint32_t)(wn * 64 + p * 16 + b_row) * LDB + kb * 32 + b_koff;  \
                uint32_t r0, r1, r2, r3;                                        \
                ldsm4(r0, r1, r2, r3, sb + (bo) + 2 * TILE_B + ro);             \
                bh[2 * p][0] = r0; bh[2 * p][1] = r1;                           \
                bh[2 * p + 1][0] = r2; bh[2 * p + 1][1] = r3;                   \
                ldsm4(r0, r1, r2, r3, sb + (bo) + 3 * TILE_B + ro);             \
                bl[2 * p][0] = r0; bl[2 * p][1] = r1;                           \
                bl[2 * p + 1][0] = r2; bl[2 * p + 1][1] = r3;                   \
            }                                                                   \
            _Pragma("unroll")                                                   \
            for (int mt = 0; mt < 2; mt++)                                      \
                _Pragma("unroll")                                               \
                for (int nt = 0; nt < 8; nt++) {                                \
                    mma16816(c[mt][nt], ah[mt], bh[nt]);                        \
                    mma16816(c[mt][nt], ah[mt], bl[nt]);                        \
                    mma16816(c[mt][nt], al[mt], bh[nt]);                        \
                }                                                               \
        }                                                                       \
    } while (0)

#define GEMM_COMMON                                                             \
    extern __shared__ __align__(16) char smem[];                                \
    const uint32_t sb = s2u(smem);                                              \
    const int t = threadIdx.x;                                                  \
    const int lane = t & 31, wid = t >> 5;                                      \
    const int wm = wid >> 1, wn = wid & 1;                                      \
    const int m0 = blockIdx.x * 128;                                            \
    const int crow = t >> 1;                                                    \
    const int cko  = (t & 1) * 16;                                              \
    const uint32_t cbase = (uint32_t)crow * LDB + (uint32_t)cko * 2;            \
    const int a_row  = lane & 15;                                               \
    const int a_koff = ((lane >> 4) & 1) * 16;                                  \
    const int b_row  = ((lane >> 4) & 1) * 8 + (lane & 7);                      \
    const int b_koff = ((lane >> 3) & 1) * 16;                                  \
    float c[2][8][4];                                                           \
    _Pragma("unroll")                                                           \
    for (int i = 0; i < 2; i++)                                                 \
        _Pragma("unroll")                                                       \
        for (int j = 0; j < 8; j++)                                             \
            _Pragma("unroll")                                                   \
            for (int q = 0; q < 4; q++) c[i][j][q] = 0.0f;                      \
    float v[16];                                                                \
    uint4 pwh[2], pwl[2];

// ---------------- half2 gather helper ----------------
__device__ __forceinline__ float4 ld_row4(const uint2* A2, int row, int lane) {
    uint2 u = A2[(size_t)row * 32 + lane];
    float2 f0 = __half22float2(*(__half2*)&u.x);
    float2 f1 = __half22float2(*(__half2*)&u.y);
    return make_float4(f0.x, f0.y, f1.x, f1.y);
}

// ---------------- GEMM1: Ah = X @ W1^T (fp16 out, unscaled) ----------------
template <int K>
__global__ __launch_bounds__(256, 1) void k_gemm_mma(const float* __restrict__ X,
                                                     const __nv_bfloat16* __restrict__ Whi,
                                                     const __nv_bfloat16* __restrict__ Wlo,
                                                     __half* __restrict__ Ah) {
    GEMM_COMMON
    const int NT = (K + 31) / 32;
    const int xr = m0 + crow;
    const bool rok = xr < N_NODES;
    const float* Xrow = X + (size_t)xr * K;

    LOADX(0, K);
    for (int ch = 0; ch < NT; ch++) {
        const uint32_t bo = (uint32_t)(ch & 1) * CH_BUF;
        CVT_STORE(bo);
        if (ch + 1 < NT) LOADX(ch + 1, K);
        __syncthreads();
        MMA_CHUNK(bo);
    }

    #pragma unroll
    for (int mt = 0; mt < 2; mt++)
        #pragma unroll
        for (int g2 = 0; g2 < 2; g2++) {
            int row = m0 + wm * 32 + mt * 16 + (lane >> 2) + g2 * 8;
            if (row < N_NODES) {
                __half* pr = Ah + (size_t)row * F1 + wn * 64 + (lane & 3) * 2;
                #pragma unroll
                for (int nt = 0; nt < 8; nt++) {
                    __half2 o = __floats2half2_rn(c[mt][nt][g2 * 2 + 0],
                                                  c[mt][nt][g2 * 2 + 1]);
                    *(__half2*)(pr + nt * 8) = o;
                }
            }
        }
}

// ---------------- FUSED: agg1 (CSR gather of Ah -> relu'd C tile in smem)
//                  + GEMM2 (C @ W2^T) + head (z = h2 @ Wlin^T) ----------------
__global__ __launch_bounds__(256, 1) void k_fused2(const __nv_bfloat16* __restrict__ Whi,
                                                   const __nv_bfloat16* __restrict__ Wlo,
                                                   const float* __restrict__ Wlin,
                                                   float* __restrict__ z) {
    GEMM_COMMON
    const int NT = 4;   // K=128

    float* Wls = (float*)(smem + WLS_OFF);
    float* Cs  = (float*)(smem + CS_OFF);
    #pragma unroll
    for (int i = 0; i < 8; i++) Wls[t + i * 256] = Wlin[t + i * 256];

    // ---- phase A: aggregate this CTA's 128 rows into Cs (warp per row) ----
    const uint2* A2 = (const uint2*)g_Ah;
    #pragma unroll 1
    for (int r = 0; r < 16; r++) {
        int row = wid * 16 + r;
        int g = m0 + row;
        float4 acc = make_float4(0.f, 0.f, 0.f, 0.f);
        if (g < N_NODES) {
            float s = g_inv[g];
            float4 vv = ld_row4(A2, g, lane);
            acc = make_float4(vv.x * s, vv.y * s, vv.z * s, vv.w * s);  // self loop
            int p  = g_start[g];
            int s1 = g_start[g + 1];
            for (; p + 8 <= s1; p += 8) {
                #pragma unroll
                for (int u8 = 0; u8 < 8; u8++) {
                    int i = g_srcl[p + u8];
                    float wi = g_inv[i];
                    float4 u = ld_row4(A2, i, lane);
                    acc.x += u.x * wi; acc.y += u.y * wi;
                    acc.z += u.z * wi; acc.w += u.w * wi;
                }
            }
            for (; p < s1; p++) {
                int i = g_srcl[p];
                float wi = g_inv[i];
                float4 u = ld_row4(A2, i, lane);
                acc.x += u.x * wi; acc.y += u.y * wi; acc.z += u.z * wi; acc.w += u.w * wi;
            }
            acc.x = fmaxf(acc.x * s, 0.f);
            acc.y = fmaxf(acc.y * s, 0.f);
            acc.z = fmaxf(acc.z * s, 0.f);
            acc.w = fmaxf(acc.w * s, 0.f);
        }
        *(float4*)&Cs[row * CSLD + lane * 4] = acc;
    }
    __syncthreads();

    // ---- phase B: GEMM from smem C tile ----
#define LOADXS(CH)                                                              \
    do {                                                                        \
        const int ks_ = (CH) * 32 + cko;                                        \
        _Pragma("unroll")                                                       \
        for (int q = 0; q < 4; q++)                                             \
            *(float4*)&v[q * 4] = *(const float4*)&Cs[crow * CSLD + ks_ + q * 4]; \
        LOADW(CH);                                                              \
    } while (0)

    LOADXS(0);
    for (int ch = 0; ch < NT; ch++) {
        const uint32_t bo = (uint32_t)(ch & 1) * CH_BUF;
        CVT_STORE(bo);
        if (ch + 1 < NT) LOADXS(ch + 1);
        __syncthreads();
        MMA_CHUNK(bo);
    }
#undef LOADXS

    // ---- stage h2 tile to smem (fp16, row stride ROWB) ----
    __syncthreads();
    #pragma unroll
    for (int mt = 0; mt < 2; mt++)
        #pragma unroll
        for (int g2 = 0; g2 < 2; g2++) {
            int row = wm * 32 + mt * 16 + (lane >> 2) + g2 * 8;
            char* pr = smem + row * ROWB + (wn * 64 + (lane & 3) * 2) * 2;
            #pragma unroll
            for (int nt = 0; nt < 8; nt++) {
                __half2 o = __floats2half2_rn(c[mt][nt][g2 * 2 + 0],
                                              c[mt][nt][g2 * 2 + 1]);
                *(__half2*)(pr + nt * 16) = o;
            }
        }
    __syncthreads();

    // ---- z: warp per row, dot with Wlin + shfl reduce ----
    #pragma unroll 1
    for (int r8 = 0; r8 < 16; r8++) {
        int row = wid * 16 + r8;
        int grow = m0 + row;
        uint2 u = *(uint2*)(smem + row * ROWB + lane * 8);
        float2 f0 = __half22float2(*(__half2*)&u.x);
        float2 f1 = __half22float2(*(__half2*)&u.y);
        #pragma unroll
        for (int cc = 0; cc < NCLS; cc++) {
            float4 wv = *(const float4*)&Wls[cc * F1 + lane * 4];
            float pd = f0.x * wv.x + f0.y * wv.y + f1.x * wv.z + f1.y * wv.w;
            pd += __shfl_xor_sync(0xffffffffu, pd, 16);
            pd += __shfl_xor_sync(0xffffffffu, pd, 8);
            pd += __shfl_xor_sync(0xffffffffu, pd, 4);
            pd += __shfl_xor_sync(0xffffffffu, pd, 2);
            pd += __shfl_xor_sync(0xffffffffu, pd, 1);
            if (lane == 0 && grow < N_NODES) z[(size_t)grow * NCLS + cc] = pd;
        }
    }
}

// ---------------- layer-2 aggregation in z-space, half-warp per dst ----------------
__global__ __launch_bounds__(256) void k_agg2z(float* __restrict__ out) {
    int t = threadIdx.x;
    int w = blockIdx.x * 16 + (t >> 4);
    int l16 = t & 15;
    if (w >= N_NODES) return;
    const float* Z = g_z;
    float s = g_inv[w];

    float acc = Z[(size_t)w * NCLS + l16] * s;   // self loop
    int p  = g_start[w];
    int s1 = g_start[w + 1];
    for (; p + 4 <= s1; p += 4) {
        int i0 = g_srcl[p], i1 = g_srcl[p + 1], i2 = g_srcl[p + 2], i3 = g_srcl[p + 3];
        float a0 = g_inv[i0] * Z[(size_t)i0 * NCLS + l16];
        float a1 = g_inv[i1] * Z[(size_t)i1 * NCLS + l16];
        float a2 = g_inv[i2] * Z[(size_t)i2 * NCLS + l16];
        float a3 = g_inv[i3] * Z[(size_t)i3 * NCLS + l16];
        acc += (a0 + a1) + (a2 + a3);
    }
    for (; p < s1; p++) {
        int i = g_srcl[p];
        acc += g_inv[i] * Z[(size_t)i * NCLS + l16];
    }
    out[(size_t)w * NCLS + l16] = acc * s;
}

// ---------------- launch: fork GEMM1 branch parallel to CSR build ----------------
extern "C" void kernel_launch(void* const* d_in, const int* in_sizes, int n_in,
                              void* d_out, int out_size) {
    const float* x    = (const float*)d_in[0];
    const void*  ei   = d_in[1];
    const float* W1   = (const float*)d_in[2];
    const float* W2   = (const float*)d_in[3];
    const float* Wlin = (const float*)d_in[4];
    float* out = (float*)d_out;

    long long E = (long long)in_sizes[1] / 2;

    __half* Ah;
    float* Zp;
    __nv_bfloat16 *w1h, *w1l, *w2h, *w2l;
    cudaGetSymbolAddress((void**)&Ah, g_Ah);
    cudaGetSymbolAddress((void**)&Zp, g_z);
    cudaGetSymbolAddress((void**)&w1h, g_W1hi);
    cudaGetSymbolAddress((void**)&w1l, g_W1lo);
    cudaGetSymbolAddress((void**)&w2h, g_W2hi);
    cudaGetSymbolAddress((void**)&w2l, g_W2lo);

    cudaFuncSetAttribute(k_gemm_mma<500>, cudaFuncAttributeMaxDynamicSharedMemorySize, GEMM_SMEM);
    cudaFuncSetAttribute(k_fused2, cudaFuncAttributeMaxDynamicSharedMemorySize, FUSED_SMEM);

    const int T = 256;
    int nodeBlocks = (N_NODES + T - 1) / T;
    int gemmBlocks = (N_NODES + 127) / 128;   // 391
    int edgeBlocks = (int)((E + T - 1) / T);
    int agg2Blocks = (N_NODES + 15) / 16;
    int wsBlocks   = (128 * 512 + T - 1) / T;

    // Fork-join inside graph capture (validated R14 pattern).
    cudaStream_t sB;
    cudaStreamCreateWithFlags(&sB, cudaStreamNonBlocking);
    cudaEvent_t e0, e1;
    cudaEventCreateWithFlags(&e0, cudaEventDisableTiming);
    cudaEventCreateWithFlags(&e1, cudaEventDisableTiming);

    cudaEventRecord(e0, 0);
    cudaStreamWaitEvent(sB, e0, 0);

    k_init<<<nodeBlocks, T>>>((const int*)ei);                              // s0 #1
    k_wsplit<<<wsBlocks, T, 0, sB>>>(W1, w1h, w1l, 500);                    // sB #2
    k_hist<<<edgeBlocks, T>>>(ei, E);                                       // s0 #3
    k_gemm_mma<500><<<gemmBlocks, T, GEMM_SMEM, sB>>>(x, w1h, w1l, Ah);     // sB #4 <- profiled
    cudaEventRecord(e1, sB);
    k_scan1<<<NB_SCAN, T>>>();                                              // s0
    k_scan2<<<1, T>>>();                                                    // s0
    k_scan3<<<NB_SCAN, T>>>();                                              // s0
    k_fill<<<edgeBlocks, T>>>(ei, E);                                       // s0
    k_wsplit<<<wsBlocks, T>>>(W2, w2h, w2l, 128);                           // s0 (hidden)
    cudaStreamWaitEvent(0, e1, 0);                                          // join
    k_fused2<<<gemmBlocks, T, FUSED_SMEM>>>(w2h, w2l, Wlin, Zp);            // s0
    k_agg2z<<<agg2Blocks, T>>>(out);                                        // s0

    cudaStreamDestroy(sB);
    cudaEventDestroy(e0);
    cudaEventDestroy(e1);
}